// round 9
// baseline (speedup 1.0000x reference)
#include <cuda_runtime.h>
#include <cuda_fp16.h>
#include <cstdint>
#include <cstddef>

static constexpr int NT = 2048;
static constexpr int NH = 1024;
static constexpr int NF = 2816;
static constexpr int NE = 8;

static constexpr int BM  = 128;   // token rows per CTA
static constexpr int BN  = 64;    // output cols per CTA
static constexpr int BK  = 32;    // k halves per stage
static constexpr int BKP = 40;    // padded row stride (80B) -> conflict-free ldmatrix
static constexpr int NTHR = 256;  // 8 warps: 4(M) x 2(N), warp tile 32x32
static constexpr int NSTG = 3;

static constexpr int STG1_H = BM * BKP + 2 * BN * BKP;  // A + B1 + B3 (halves)
static constexpr int STG2_H = BM * BKP + BN * BKP;      // A + B
static constexpr int SMEM1 = NSTG * STG1_H * 2;         // 61440 B
static constexpr int SMEM2 = NSTG * STG2_H * 2;         // 46080 B

// ---------------- device scratch ----------------
__device__ int   g_cnt[NE];
__device__ int   g_tok[NE][NT];
__device__ float g_rw[NE][NT];
__device__ __align__(16) __half g_xh [(size_t)NT * NH];
__device__ __align__(16) __half g_w1h[(size_t)NE * NF * NH];
__device__ __align__(16) __half g_w3h[(size_t)NE * NF * NH];
__device__ __align__(16) __half g_w2h[(size_t)NE * NH * NF];
__device__ __align__(16) __half g_hbuf[(size_t)NE * NT * NF];

// ---------------- helpers ----------------
static __device__ __forceinline__ uint32_t smaddr(const void* p) {
    return (uint32_t)__cvta_generic_to_shared(p);
}
static __device__ __forceinline__ void ldm4(uint32_t& r0, uint32_t& r1, uint32_t& r2, uint32_t& r3, uint32_t a) {
    asm volatile("ldmatrix.sync.aligned.m8n8.x4.shared.b16 {%0,%1,%2,%3}, [%4];\n"
                 : "=r"(r0), "=r"(r1), "=r"(r2), "=r"(r3) : "r"(a));
}
static __device__ __forceinline__ void mma16816(float c[4], const uint32_t a[4], const uint32_t b[2]) {
    asm volatile("mma.sync.aligned.m16n8k16.row.col.f32.f16.f16.f32 "
                 "{%0,%1,%2,%3},{%4,%5,%6,%7},{%8,%9},{%0,%1,%2,%3};\n"
                 : "+f"(c[0]), "+f"(c[1]), "+f"(c[2]), "+f"(c[3])
                 : "r"(a[0]), "r"(a[1]), "r"(a[2]), "r"(a[3]), "r"(b[0]), "r"(b[1]));
}
static __device__ __forceinline__ void cp16(void* dst, const void* src) {
    asm volatile("cp.async.cg.shared.global [%0], [%1], 16;\n" :: "r"(smaddr(dst)), "l"(src));
}
static __device__ __forceinline__ void cp_commit()  { asm volatile("cp.async.commit_group;\n"); }
static __device__ __forceinline__ void cp_wait1()   { asm volatile("cp.async.wait_group 1;\n"); }

// ---------------- small kernels ----------------
__global__ void k_zero() {
    if (threadIdx.x < NE) g_cnt[threadIdx.x] = 0;
}

__global__ void k_convx(const float* __restrict__ x) {
    size_t i = ((size_t)blockIdx.x * blockDim.x + threadIdx.x) * 4;
    float4 v = *(const float4*)(x + i);
    *(__half2*)(g_xh + i)     = __floats2half2_rn(v.x, v.y);
    *(__half2*)(g_xh + i + 2) = __floats2half2_rn(v.z, v.w);
}

// which: 0 -> g_w1h, 1 -> g_w3h, 2 -> g_w2h  (device-side symbol resolution:
// passing a __device__ array from host code yields the host shadow address,
// which GB300's ATS happily writes to -- silently wrong. Resolve on device.)
__global__ void k_convw(const float* __restrict__ s, int which) {
    __half* d = (which == 0) ? g_w1h : (which == 1) ? g_w3h : g_w2h;
    size_t i = ((size_t)blockIdx.x * blockDim.x + threadIdx.x) * 8;
    float4 a = *(const float4*)(s + i);
    float4 b = *(const float4*)(s + i + 4);
    __half2 h0 = __floats2half2_rn(a.x, a.y);
    __half2 h1 = __floats2half2_rn(a.z, a.w);
    __half2 h2 = __floats2half2_rn(b.x, b.y);
    __half2 h3 = __floats2half2_rn(b.z, b.w);
    uint4 o;
    o.x = *(uint32_t*)&h0; o.y = *(uint32_t*)&h1; o.z = *(uint32_t*)&h2; o.w = *(uint32_t*)&h3;
    *(uint4*)(d + i) = o;
}

__global__ void k_router(const float* __restrict__ x, const float* __restrict__ gw) {
    int t = blockIdx.x * 8 + (threadIdx.x >> 5);
    int lane = threadIdx.x & 31;
    const float* xr = x + (size_t)t * NH;
    float acc[NE];
#pragma unroll
    for (int e = 0; e < NE; e++) acc[e] = 0.f;
    for (int h = lane; h < NH; h += 32) {
        float xv = xr[h];
#pragma unroll
        for (int e = 0; e < NE; e++) acc[e] += xv * gw[e * NH + h];
    }
#pragma unroll
    for (int e = 0; e < NE; e++)
        for (int o = 16; o > 0; o >>= 1) acc[e] += __shfl_xor_sync(0xffffffffu, acc[e], o);
    if (lane == 0) {
        int i0 = 0; float v0 = acc[0];
#pragma unroll
        for (int e = 1; e < NE; e++) if (acc[e] > v0) { v0 = acc[e]; i0 = e; }
        int i1 = -1; float v1 = -1e30f;
#pragma unroll
        for (int e = 0; e < NE; e++) if (e != i0 && acc[e] > v1) { v1 = acc[e]; i1 = e; }
        float w0 = 1.f / (1.f + expf(v1 - v0));
        float w1 = 1.f - w0;
        int p0 = atomicAdd(&g_cnt[i0], 1); g_tok[i0][p0] = t; g_rw[i0][p0] = w0;
        int p1 = atomicAdd(&g_cnt[i1], 1); g_tok[i1][p1] = t; g_rw[i1][p1] = w1;
    }
}

// ---------------- FFN1: h = silu(x w1^T) * (x w3^T) ----------------
__global__ __launch_bounds__(NTHR, 2) void k_ffn1() {
    const int e   = blockIdx.z;
    const int cnt = g_cnt[e];
    const int m0  = blockIdx.y * BM;
    if (m0 >= cnt) return;
    const int n0  = blockIdx.x * BN;

    extern __shared__ __align__(16) __half sm[];

    const int tid  = threadIdx.x;
    const int lane = tid & 31, wid = tid >> 5;
    const int wm = (wid & 3) * 32, wn = (wid >> 2) * 32;

    const __half* w1e = g_w1h + (size_t)e * NF * NH;
    const __half* w3e = g_w3h + (size_t)e * NF * NH;

    const __half* aP[2]; int aOff[2];
#pragma unroll
    for (int it = 0; it < 2; it++) {
        int idx = tid + it * NTHR;
        int row = idx >> 2, ch = idx & 3;
        int gi = m0 + row; if (gi > cnt - 1) gi = cnt - 1;
        aP[it]   = g_xh + (size_t)g_tok[e][gi] * NH + ch * 8;
        aOff[it] = row * BKP + ch * 8;
    }
    const int brow = tid >> 2, bch = tid & 3;
    const __half* b1P = w1e + (size_t)(n0 + brow) * NH + bch * 8;
    const __half* b3P = w3e + (size_t)(n0 + brow) * NH + bch * 8;
    const int bOff = brow * BKP + bch * 8;

    auto fill = [&](int st, int kt) {
        __half* A  = sm + st * STG1_H;
        __half* B1 = A + BM * BKP;
        __half* B3 = B1 + BN * BKP;
        int k0 = kt * BK;
        cp16(A + aOff[0], aP[0] + k0);
        cp16(A + aOff[1], aP[1] + k0);
        cp16(B1 + bOff, b1P + k0);
        cp16(B3 + bOff, b3P + k0);
    };

    float accG[2][4][4], accU[2][4][4];
#pragma unroll
    for (int i = 0; i < 2; i++)
#pragma unroll
        for (int j = 0; j < 4; j++)
#pragma unroll
            for (int k = 0; k < 4; k++) { accG[i][j][k] = 0.f; accU[i][j][k] = 0.f; }

    const int KT = NH / BK;   // 32
    fill(0, 0); cp_commit();
    fill(1, 1); cp_commit();

    for (int kt = 0; kt < KT; kt++) {
        const int cur = kt % NSTG;
        cp_wait1();
        __syncthreads();

        const __half* A  = sm + cur * STG1_H;
        const __half* B1 = A + BM * BKP;
        const __half* B3 = B1 + BN * BKP;

#pragma unroll
        for (int ks = 0; ks < 2; ks++) {
            uint32_t af[2][4];
#pragma unroll
            for (int mi = 0; mi < 2; mi++) {
                uint32_t a = smaddr(A + (wm + mi * 16 + (lane & 15)) * BKP + ks * 16 + (lane >> 4) * 8);
                ldm4(af[mi][0], af[mi][1], af[mi][2], af[mi][3], a);
            }
            uint32_t b1f[4][2], b3f[4][2];
#pragma unroll
            for (int np = 0; np < 2; np++) {
                int j    = lane >> 3;
                int nrow = wn + np * 16 + (j >> 1) * 8 + (lane & 7);
                int kcol = ks * 16 + (j & 1) * 8;
                ldm4(b1f[2 * np][0], b1f[2 * np][1], b1f[2 * np + 1][0], b1f[2 * np + 1][1],
                     smaddr(B1 + nrow * BKP + kcol));
                ldm4(b3f[2 * np][0], b3f[2 * np][1], b3f[2 * np + 1][0], b3f[2 * np + 1][1],
                     smaddr(B3 + nrow * BKP + kcol));
            }
#pragma unroll
            for (int mi = 0; mi < 2; mi++)
#pragma unroll
                for (int ni = 0; ni < 4; ni++) {
                    mma16816(accG[mi][ni], af[mi], b1f[ni]);
                    mma16816(accU[mi][ni], af[mi], b3f[ni]);
                }
        }

        if (kt + 2 < KT) fill((kt + 2) % NSTG, kt + 2);
        cp_commit();
    }

#pragma unroll
    for (int mi = 0; mi < 2; mi++)
#pragma unroll
        for (int ni = 0; ni < 4; ni++)
#pragma unroll
            for (int p = 0; p < 2; p++) {
                int row = m0 + wm + mi * 16 + (lane >> 2) + p * 8;
                int col = n0 + wn + ni * 8 + (lane & 3) * 2;
                float g0 = accG[mi][ni][2 * p], g1 = accG[mi][ni][2 * p + 1];
                float u0 = accU[mi][ni][2 * p], u1 = accU[mi][ni][2 * p + 1];
                float h0 = g0 / (1.f + __expf(-g0)) * u0;
                float h1 = g1 / (1.f + __expf(-g1)) * u1;
                *(__half2*)&g_hbuf[((size_t)e * NT + row) * NF + col] = __floats2half2_rn(h0, h1);
            }
}

// ---------------- FFN2: y = h w2^T, scaled atomic scatter ----------------
__global__ __launch_bounds__(NTHR, 2) void k_ffn2(float* __restrict__ out) {
    const int e   = blockIdx.z;
    const int cnt = g_cnt[e];
    const int m0  = blockIdx.y * BM;
    if (m0 >= cnt) return;
    const int n0  = blockIdx.x * BN;

    extern __shared__ __align__(16) __half sm[];

    const int tid  = threadIdx.x;
    const int lane = tid & 31, wid = tid >> 5;
    const int wm = (wid & 3) * 32, wn = (wid >> 2) * 32;

    const __half* w2e = g_w2h + (size_t)e * NH * NF;
    const __half* hb  = g_hbuf + (size_t)e * NT * NF;

    const __half* aP[2]; int aOff[2];
#pragma unroll
    for (int it = 0; it < 2; it++) {
        int idx = tid + it * NTHR;
        int row = idx >> 2, ch = idx & 3;
        aP[it]   = hb + (size_t)(m0 + row) * NF + ch * 8;
        aOff[it] = row * BKP + ch * 8;
    }
    const int brow = tid >> 2, bch = tid & 3;
    const __half* bP = w2e + (size_t)(n0 + brow) * NF + bch * 8;
    const int bOff = brow * BKP + bch * 8;

    auto fill = [&](int st, int kt) {
        __half* A = sm + st * STG2_H;
        __half* B = A + BM * BKP;
        int k0 = kt * BK;
        cp16(A + aOff[0], aP[0] + k0);
        cp16(A + aOff[1], aP[1] + k0);
        cp16(B + bOff, bP + k0);
    };

    float acc[2][4][4];
#pragma unroll
    for (int i = 0; i < 2; i++)
#pragma unroll
        for (int j = 0; j < 4; j++)
#pragma unroll
            for (int k = 0; k < 4; k++) acc[i][j][k] = 0.f;

    const int KT = NF / BK;   // 88
    fill(0, 0); cp_commit();
    fill(1, 1); cp_commit();

    for (int kt = 0; kt < KT; kt++) {
        const int cur = kt % NSTG;
        cp_wait1();
        __syncthreads();

        const __half* A = sm + cur * STG2_H;
        const __half* B = A + BM * BKP;

#pragma unroll
        for (int ks = 0; ks < 2; ks++) {
            uint32_t af[2][4];
#pragma unroll
            for (int mi = 0; mi < 2; mi++) {
                uint32_t a = smaddr(A + (wm + mi * 16 + (lane & 15)) * BKP + ks * 16 + (lane >> 4) * 8);
                ldm4(af[mi][0], af[mi][1], af[mi][2], af[mi][3], a);
            }
            uint32_t bf[4][2];
#pragma unroll
            for (int np = 0; np < 2; np++) {
                int j    = lane >> 3;
                int nrow = wn + np * 16 + (j >> 1) * 8 + (lane & 7);
                int kcol = ks * 16 + (j & 1) * 8;
                ldm4(bf[2 * np][0], bf[2 * np][1], bf[2 * np + 1][0], bf[2 * np + 1][1],
                     smaddr(B + nrow * BKP + kcol));
            }
#pragma unroll
            for (int mi = 0; mi < 2; mi++)
#pragma unroll
                for (int ni = 0; ni < 4; ni++)
                    mma16816(acc[mi][ni], af[mi], bf[ni]);
        }

        if (kt + 2 < KT) fill((kt + 2) % NSTG, kt + 2);
        cp_commit();
    }

#pragma unroll
    for (int mi = 0; mi < 2; mi++)
#pragma unroll
        for (int ni = 0; ni < 4; ni++)
#pragma unroll
            for (int p = 0; p < 2; p++) {
                int slot = m0 + wm + mi * 16 + (lane >> 2) + p * 8;
                if (slot < cnt) {
                    int   t  = g_tok[e][slot];
                    float rw = g_rw[e][slot];
                    int col = n0 + wn + ni * 8 + (lane & 3) * 2;
                    atomicAdd(&out[(size_t)t * NH + col],     rw * acc[mi][ni][2 * p]);
                    atomicAdd(&out[(size_t)t * NH + col + 1], rw * acc[mi][ni][2 * p + 1]);
                }
            }
}

// ---------------- launch ----------------
extern "C" void kernel_launch(void* const* d_in, const int* in_sizes, int n_in,
                              void* d_out, int out_size) {
    const float* x  = (const float*)d_in[0];
    const float* gw = (const float*)d_in[1];
    const float* w1 = (const float*)d_in[2];
    const float* w3 = (const float*)d_in[3];
    const float* w2 = (const float*)d_in[4];
    float* out = (float*)d_out;

    cudaFuncSetAttribute(k_ffn1, cudaFuncAttributeMaxDynamicSharedMemorySize, SMEM1);
    cudaFuncSetAttribute(k_ffn2, cudaFuncAttributeMaxDynamicSharedMemorySize, SMEM2);

    cudaMemsetAsync(out, 0, (size_t)NT * NH * sizeof(float));
    k_zero<<<1, 32>>>();
    k_convx<<<(NT * NH / 4) / 256, 256>>>(x);
    const int WBLK = (NE * NF * NH) / (256 * 8);   // 11264
    k_convw<<<WBLK, 256>>>(w1, 0);
    k_convw<<<WBLK, 256>>>(w3, 1);
    k_convw<<<WBLK, 256>>>(w2, 2);
    k_router<<<NT / 8, 256>>>(x, gw);
    k_ffn1<<<dim3(NF / BN, NT / BM, NE), NTHR, SMEM1>>>();
    k_ffn2<<<dim3(NH / BN, NT / BM, NE), NTHR, SMEM2>>>(out);
}

// round 10
// speedup vs baseline: 1.5962x; 1.5962x over previous
#include <cuda_runtime.h>
#include <cuda_fp16.h>
#include <cstdint>
#include <cstddef>

static constexpr int NT = 2048;
static constexpr int NH = 1024;
static constexpr int NF = 2816;
static constexpr int NE = 8;

static constexpr int BM  = 128;   // token rows per CTA
static constexpr int BN  = 128;   // output cols per CTA
static constexpr int BK  = 64;    // k halves per stage
static constexpr int BKP = 72;    // padded row stride in halves (144B) -> conflict-free ldmatrix
static constexpr int NTHR = 512;  // 16 warps: 4(M) x 4(N), warp tile 32x32
static constexpr int NSTG = 3;

static constexpr int STG1_H = BM * BKP + 2 * BN * BKP;  // A + B1 + B3 (halves) = 27648
static constexpr int STG2_H = BM * BKP + BN * BKP;      // A + B            = 18432
static constexpr int SMEM1 = NSTG * STG1_H * 2;         // 165888 B
static constexpr int SMEM2 = NSTG * STG2_H * 2;         // 110592 B

// ---------------- device scratch ----------------
__device__ int   g_cnt[NE];
__device__ int   g_tok[NE][NT];
__device__ float g_rw[NE][NT];
__device__ __align__(16) __half g_xh [(size_t)NT * NH];
__device__ __align__(16) __half g_w1h[(size_t)NE * NF * NH];
__device__ __align__(16) __half g_w3h[(size_t)NE * NF * NH];
__device__ __align__(16) __half g_w2h[(size_t)NE * NH * NF];
__device__ __align__(16) __half g_hbuf[(size_t)NE * NT * NF];

// ---------------- helpers ----------------
static __device__ __forceinline__ uint32_t smaddr(const void* p) {
    return (uint32_t)__cvta_generic_to_shared(p);
}
static __device__ __forceinline__ void ldm4(uint32_t& r0, uint32_t& r1, uint32_t& r2, uint32_t& r3, uint32_t a) {
    asm volatile("ldmatrix.sync.aligned.m8n8.x4.shared.b16 {%0,%1,%2,%3}, [%4];\n"
                 : "=r"(r0), "=r"(r1), "=r"(r2), "=r"(r3) : "r"(a));
}
static __device__ __forceinline__ void mma16816(float c[4], const uint32_t a[4], const uint32_t b[2]) {
    asm volatile("mma.sync.aligned.m16n8k16.row.col.f32.f16.f16.f32 "
                 "{%0,%1,%2,%3},{%4,%5,%6,%7},{%8,%9},{%0,%1,%2,%3};\n"
                 : "+f"(c[0]), "+f"(c[1]), "+f"(c[2]), "+f"(c[3])
                 : "r"(a[0]), "r"(a[1]), "r"(a[2]), "r"(a[3]), "r"(b[0]), "r"(b[1]));
}
static __device__ __forceinline__ void cp16(void* dst, const void* src) {
    asm volatile("cp.async.cg.shared.global [%0], [%1], 16;\n" :: "r"(smaddr(dst)), "l"(src));
}
static __device__ __forceinline__ void cp_commit()  { asm volatile("cp.async.commit_group;\n"); }
static __device__ __forceinline__ void cp_wait1()   { asm volatile("cp.async.wait_group 1;\n"); }

// ---------------- small kernels ----------------
__global__ void k_zero() {
    if (threadIdx.x < NE) g_cnt[threadIdx.x] = 0;
}

__global__ void k_convx(const float* __restrict__ x) {
    size_t i = ((size_t)blockIdx.x * blockDim.x + threadIdx.x) * 4;
    float4 v = *(const float4*)(x + i);
    *(__half2*)(g_xh + i)     = __floats2half2_rn(v.x, v.y);
    *(__half2*)(g_xh + i + 2) = __floats2half2_rn(v.z, v.w);
}

// which: 0 -> g_w1h, 1 -> g_w3h, 2 -> g_w2h (resolve device symbol on device;
// host-passed __device__ symbol = host shadow addr, silently wrong via ATS)
__global__ void k_convw(const float* __restrict__ s, int which) {
    __half* d = (which == 0) ? g_w1h : (which == 1) ? g_w3h : g_w2h;
    size_t i = ((size_t)blockIdx.x * blockDim.x + threadIdx.x) * 8;
    float4 a = *(const float4*)(s + i);
    float4 b = *(const float4*)(s + i + 4);
    __half2 h0 = __floats2half2_rn(a.x, a.y);
    __half2 h1 = __floats2half2_rn(a.z, a.w);
    __half2 h2 = __floats2half2_rn(b.x, b.y);
    __half2 h3 = __floats2half2_rn(b.z, b.w);
    uint4 o;
    o.x = *(uint32_t*)&h0; o.y = *(uint32_t*)&h1; o.z = *(uint32_t*)&h2; o.w = *(uint32_t*)&h3;
    *(uint4*)(d + i) = o;
}

__global__ void k_router(const float* __restrict__ x, const float* __restrict__ gw) {
    int t = blockIdx.x * 8 + (threadIdx.x >> 5);
    int lane = threadIdx.x & 31;
    const float* xr = x + (size_t)t * NH;
    float acc[NE];
#pragma unroll
    for (int e = 0; e < NE; e++) acc[e] = 0.f;
    for (int h = lane; h < NH; h += 32) {
        float xv = xr[h];
#pragma unroll
        for (int e = 0; e < NE; e++) acc[e] += xv * gw[e * NH + h];
    }
#pragma unroll
    for (int e = 0; e < NE; e++)
        for (int o = 16; o > 0; o >>= 1) acc[e] += __shfl_xor_sync(0xffffffffu, acc[e], o);
    if (lane == 0) {
        int i0 = 0; float v0 = acc[0];
#pragma unroll
        for (int e = 1; e < NE; e++) if (acc[e] > v0) { v0 = acc[e]; i0 = e; }
        int i1 = -1; float v1 = -1e30f;
#pragma unroll
        for (int e = 0; e < NE; e++) if (e != i0 && acc[e] > v1) { v1 = acc[e]; i1 = e; }
        float w0 = 1.f / (1.f + expf(v1 - v0));
        float w1 = 1.f - w0;
        int p0 = atomicAdd(&g_cnt[i0], 1); g_tok[i0][p0] = t; g_rw[i0][p0] = w0;
        int p1 = atomicAdd(&g_cnt[i1], 1); g_tok[i1][p1] = t; g_rw[i1][p1] = w1;
    }
}

// ---------------- FFN1: h = silu(x w1^T) * (x w3^T) ----------------
__global__ __launch_bounds__(NTHR, 1) void k_ffn1() {
    const int e   = blockIdx.z;
    const int cnt = g_cnt[e];
    const int m0  = blockIdx.y * BM;
    if (m0 >= cnt) return;
    const int n0  = blockIdx.x * BN;

    extern __shared__ __align__(16) __half sm[];

    const int tid  = threadIdx.x;
    const int lane = tid & 31, wid = tid >> 5;
    const int wm = (wid & 3) * 32, wn = (wid >> 2) * 32;

    const __half* w1e = g_w1h + (size_t)e * NF * NH;
    const __half* w3e = g_w3h + (size_t)e * NF * NH;

    // tile rows: 128 rows x 128B = 1024 16B-chunks; 512 threads -> 2 chunks each
    const __half* aP[2]; const __half* b1P[2]; const __half* b3P[2]; int tOff[2];
#pragma unroll
    for (int it = 0; it < 2; it++) {
        int idx = tid + it * NTHR;          // 0..1023
        int row = idx >> 3, ch = idx & 7;
        tOff[it] = row * BKP + ch * 8;
        int gi = m0 + row; if (gi > cnt - 1) gi = cnt - 1;
        aP[it]  = g_xh + (size_t)g_tok[e][gi] * NH + ch * 8;
        b1P[it] = w1e + (size_t)(n0 + row) * NH + ch * 8;
        b3P[it] = w3e + (size_t)(n0 + row) * NH + ch * 8;
    }

    auto fill = [&](int st, int kt) {
        __half* A  = sm + st * STG1_H;
        __half* B1 = A + BM * BKP;
        __half* B3 = B1 + BN * BKP;
        int k0 = kt * BK;
#pragma unroll
        for (int it = 0; it < 2; it++) {
            cp16(A  + tOff[it], aP[it]  + k0);
            cp16(B1 + tOff[it], b1P[it] + k0);
            cp16(B3 + tOff[it], b3P[it] + k0);
        }
    };

    float accG[2][4][4], accU[2][4][4];
#pragma unroll
    for (int i = 0; i < 2; i++)
#pragma unroll
        for (int j = 0; j < 4; j++)
#pragma unroll
            for (int k = 0; k < 4; k++) { accG[i][j][k] = 0.f; accU[i][j][k] = 0.f; }

    const int KT = NH / BK;   // 16
    fill(0, 0); cp_commit();
    fill(1, 1); cp_commit();

    for (int kt = 0; kt < KT; kt++) {
        const int cur = kt % NSTG;
        cp_wait1();
        __syncthreads();

        const __half* A  = sm + cur * STG1_H;
        const __half* B1 = A + BM * BKP;
        const __half* B3 = B1 + BN * BKP;

#pragma unroll
        for (int ks = 0; ks < 4; ks++) {      // 4 x K=16 within BK=64
            uint32_t af[2][4];
#pragma unroll
            for (int mi = 0; mi < 2; mi++) {
                uint32_t a = smaddr(A + (wm + mi * 16 + (lane & 15)) * BKP + ks * 16 + (lane >> 4) * 8);
                ldm4(af[mi][0], af[mi][1], af[mi][2], af[mi][3], a);
            }
            uint32_t b1f[4][2], b3f[4][2];
#pragma unroll
            for (int np = 0; np < 2; np++) {
                int j    = lane >> 3;
                int nrow = wn + np * 16 + (j >> 1) * 8 + (lane & 7);
                int kcol = ks * 16 + (j & 1) * 8;
                ldm4(b1f[2 * np][0], b1f[2 * np][1], b1f[2 * np + 1][0], b1f[2 * np + 1][1],
                     smaddr(B1 + nrow * BKP + kcol));
                ldm4(b3f[2 * np][0], b3f[2 * np][1], b3f[2 * np + 1][0], b3f[2 * np + 1][1],
                     smaddr(B3 + nrow * BKP + kcol));
            }
#pragma unroll
            for (int mi = 0; mi < 2; mi++)
#pragma unroll
                for (int ni = 0; ni < 4; ni++) {
                    mma16816(accG[mi][ni], af[mi], b1f[ni]);
                    mma16816(accU[mi][ni], af[mi], b3f[ni]);
                }
        }

        if (kt + 2 < KT) fill((kt + 2) % NSTG, kt + 2);
        cp_commit();
    }

#pragma unroll
    for (int mi = 0; mi < 2; mi++)
#pragma unroll
        for (int ni = 0; ni < 4; ni++)
#pragma unroll
            for (int p = 0; p < 2; p++) {
                int row = m0 + wm + mi * 16 + (lane >> 2) + p * 8;
                int col = n0 + wn + ni * 8 + (lane & 3) * 2;
                float g0 = accG[mi][ni][2 * p], g1 = accG[mi][ni][2 * p + 1];
                float u0 = accU[mi][ni][2 * p], u1 = accU[mi][ni][2 * p + 1];
                float h0 = g0 / (1.f + __expf(-g0)) * u0;
                float h1 = g1 / (1.f + __expf(-g1)) * u1;
                *(__half2*)&g_hbuf[((size_t)e * NT + row) * NF + col] = __floats2half2_rn(h0, h1);
            }
}

// ---------------- FFN2: y = h w2^T, scaled atomic scatter ----------------
__global__ __launch_bounds__(NTHR, 1) void k_ffn2(float* __restrict__ out) {
    const int e   = blockIdx.z;
    const int cnt = g_cnt[e];
    const int m0  = blockIdx.y * BM;
    if (m0 >= cnt) return;
    const int n0  = blockIdx.x * BN;

    extern __shared__ __align__(16) __half sm[];

    const int tid  = threadIdx.x;
    const int lane = tid & 31, wid = tid >> 5;
    const int wm = (wid & 3) * 32, wn = (wid >> 2) * 32;

    const __half* w2e = g_w2h + (size_t)e * NH * NF;
    const __half* hb  = g_hbuf + (size_t)e * NT * NF;

    const __half* aP[2]; const __half* bP[2]; int tOff[2];
#pragma unroll
    for (int it = 0; it < 2; it++) {
        int idx = tid + it * NTHR;
        int row = idx >> 3, ch = idx & 7;
        tOff[it] = row * BKP + ch * 8;
        aP[it] = hb  + (size_t)(m0 + row) * NF + ch * 8;
        bP[it] = w2e + (size_t)(n0 + row) * NF + ch * 8;
    }

    auto fill = [&](int st, int kt) {
        __half* A = sm + st * STG2_H;
        __half* B = A + BM * BKP;
        int k0 = kt * BK;
#pragma unroll
        for (int it = 0; it < 2; it++) {
            cp16(A + tOff[it], aP[it] + k0);
            cp16(B + tOff[it], bP[it] + k0);
        }
    };

    float acc[2][4][4];
#pragma unroll
    for (int i = 0; i < 2; i++)
#pragma unroll
        for (int j = 0; j < 4; j++)
#pragma unroll
            for (int k = 0; k < 4; k++) acc[i][j][k] = 0.f;

    const int KT = NF / BK;   // 44
    fill(0, 0); cp_commit();
    fill(1, 1); cp_commit();

    for (int kt = 0; kt < KT; kt++) {
        const int cur = kt % NSTG;
        cp_wait1();
        __syncthreads();

        const __half* A = sm + cur * STG2_H;
        const __half* B = A + BM * BKP;

#pragma unroll
        for (int ks = 0; ks < 4; ks++) {
            uint32_t af[2][4];
#pragma unroll
            for (int mi = 0; mi < 2; mi++) {
                uint32_t a = smaddr(A + (wm + mi * 16 + (lane & 15)) * BKP + ks * 16 + (lane >> 4) * 8);
                ldm4(af[mi][0], af[mi][1], af[mi][2], af[mi][3], a);
            }
            uint32_t bf[4][2];
#pragma unroll
            for (int np = 0; np < 2; np++) {
                int j    = lane >> 3;
                int nrow = wn + np * 16 + (j >> 1) * 8 + (lane & 7);
                int kcol = ks * 16 + (j & 1) * 8;
                ldm4(bf[2 * np][0], bf[2 * np][1], bf[2 * np + 1][0], bf[2 * np + 1][1],
                     smaddr(B + nrow * BKP + kcol));
            }
#pragma unroll
            for (int mi = 0; mi < 2; mi++)
#pragma unroll
                for (int ni = 0; ni < 4; ni++)
                    mma16816(acc[mi][ni], af[mi], bf[ni]);
        }

        if (kt + 2 < KT) fill((kt + 2) % NSTG, kt + 2);
        cp_commit();
    }

#pragma unroll
    for (int mi = 0; mi < 2; mi++)
#pragma unroll
        for (int ni = 0; ni < 4; ni++)
#pragma unroll
            for (int p = 0; p < 2; p++) {
                int slot = m0 + wm + mi * 16 + (lane >> 2) + p * 8;
                if (slot < cnt) {
                    int   t  = g_tok[e][slot];
                    float rw = g_rw[e][slot];
                    int col = n0 + wn + ni * 8 + (lane & 3) * 2;
                    atomicAdd(&out[(size_t)t * NH + col],     rw * acc[mi][ni][2 * p]);
                    atomicAdd(&out[(size_t)t * NH + col + 1], rw * acc[mi][ni][2 * p + 1]);
                }
            }
}

// ---------------- launch ----------------
extern "C" void kernel_launch(void* const* d_in, const int* in_sizes, int n_in,
                              void* d_out, int out_size) {
    const float* x  = (const float*)d_in[0];
    const float* gw = (const float*)d_in[1];
    const float* w1 = (const float*)d_in[2];
    const float* w3 = (const float*)d_in[3];
    const float* w2 = (const float*)d_in[4];
    float* out = (float*)d_out;

    cudaFuncSetAttribute(k_ffn1, cudaFuncAttributeMaxDynamicSharedMemorySize, SMEM1);
    cudaFuncSetAttribute(k_ffn2, cudaFuncAttributeMaxDynamicSharedMemorySize, SMEM2);

    cudaMemsetAsync(out, 0, (size_t)NT * NH * sizeof(float));
    k_zero<<<1, 32>>>();
    k_convx<<<(NT * NH / 4) / 256, 256>>>(x);
    const int WBLK = (NE * NF * NH) / (256 * 8);   // 11264
    k_convw<<<WBLK, 256>>>(w1, 0);
    k_convw<<<WBLK, 256>>>(w3, 1);
    k_convw<<<WBLK, 256>>>(w2, 2);
    k_router<<<NT / 8, 256>>>(x, gw);
    k_ffn1<<<dim3(NF / BN, NT / BM, NE), NTHR, SMEM1>>>();
    k_ffn2<<<dim3(NH / BN, NT / BM, NE), NTHR, SMEM2>>>(out);
}